// round 5
// baseline (speedup 1.0000x reference)
#include <cuda_runtime.h>
#include <cstdint>

#define SEQ 512
#define BATCH 64
#define IDIM 1024
#define HDIM 1024
#define G3 3072
#define CHUNK 64
#define NCHUNK (SEQ / CHUNK)
#define NCTA 128

// ---------------- scratch ----------------
__device__ float g_gx2[2][(size_t)CHUNK * BATCH * G3]; // double-buffered gx (2x50MB)
__device__ float g_h[BATCH * HDIM];
__device__ float g_z[BATCH * HDIM];
__device__ float g_rh[BATCH * HDIM];

// ---------------- software grid barrier ----------------
__device__ unsigned int g_bar_gen = 0;
__device__ unsigned int g_bar_cnt = 0;

__device__ __forceinline__ void grid_sync()
{
    __syncthreads();
    if (threadIdx.x == 0) {
        unsigned int gen = *(volatile unsigned int*)&g_bar_gen;
        __threadfence();
        if (atomicAdd(&g_bar_cnt, 1u) == (unsigned)NCTA - 1u) {
            g_bar_cnt = 0;
            __threadfence();
            *(volatile unsigned int*)&g_bar_gen = gen + 1u;
        } else {
            while (*(volatile unsigned int*)&g_bar_gen == gen) __nanosleep(32);
        }
        __threadfence();
    }
    __syncthreads();
}

// ---------------- gx GEMM: writes g_gx2[buf] ----------------
__global__ void __launch_bounds__(256) gemm_gx_kernel(
    const float* __restrict__ A, const float* __restrict__ W,
    const float* __restrict__ bias, int buf)
{
    __shared__ float As[16][132];
    __shared__ float Bs[16][68];

    float* gx = g_gx2[buf];
    const int bm = blockIdx.y * 128;
    const int bn = blockIdx.x * 64;
    const int tid = threadIdx.x;

    float acc[8][4];
#pragma unroll
    for (int i = 0; i < 8; i++)
#pragma unroll
        for (int j = 0; j < 4; j++) acc[i][j] = 0.f;

    const int tx = tid & 15;
    const int ty = tid >> 4;

    for (int k0 = 0; k0 < IDIM; k0 += 16) {
#pragma unroll
        for (int j = 0; j < 2; j++) {
            int lid = tid + j * 256;
            int row = lid >> 2;
            int kk  = (lid & 3) * 4;
            float4 v = *(const float4*)&A[(size_t)(bm + row) * IDIM + k0 + kk];
            As[kk + 0][row] = v.x; As[kk + 1][row] = v.y;
            As[kk + 2][row] = v.z; As[kk + 3][row] = v.w;
        }
        {
            int row = tid >> 2;
            int kk  = (tid & 3) * 4;
            float4 v = *(const float4*)&W[(size_t)(bn + row) * IDIM + k0 + kk];
            Bs[kk + 0][row] = v.x; Bs[kk + 1][row] = v.y;
            Bs[kk + 2][row] = v.z; Bs[kk + 3][row] = v.w;
        }
        __syncthreads();

#pragma unroll
        for (int kk = 0; kk < 16; kk++) {
            float4 a0 = *(const float4*)&As[kk][ty * 8];
            float4 a1 = *(const float4*)&As[kk][ty * 8 + 4];
            float4 b  = *(const float4*)&Bs[kk][tx * 4];
            float a[8] = {a0.x, a0.y, a0.z, a0.w, a1.x, a1.y, a1.z, a1.w};
            float bb[4] = {b.x, b.y, b.z, b.w};
#pragma unroll
            for (int i = 0; i < 8; i++)
#pragma unroll
                for (int j = 0; j < 4; j++) acc[i][j] += a[i] * bb[j];
        }
        __syncthreads();
    }

#pragma unroll
    for (int i = 0; i < 8; i++) {
        int m = bm + ty * 8 + i;
#pragma unroll
        for (int j = 0; j < 4; j++) {
            int n = bn + tx * 4 + j;
            gx[(size_t)m * G3 + n] = acc[i][j] + bias[n];
        }
    }
}

// ---------------- init h ----------------
__global__ void init_h_kernel(const float* __restrict__ h0)
{
    int i = blockIdx.x * blockDim.x + threadIdx.x;
    if (i < BATCH * HDIM) g_h[i] = h0[i];
}

// ---------------- persistent recurrence (pipelined) ----------------
// smem: WA[1024][16], WB[1024][8], Hs[2][32*66]
#define SM_WB 16384
#define SM_HS 24576
#define SMEM_FLOATS (24576 + 2 * 2112)

__global__ void __launch_bounds__(256, 1) recurrence_kernel(
    int c0, int buf, const float* __restrict__ Whh, const float* __restrict__ bhh,
    float* __restrict__ Y)
{
    extern __shared__ float smem[];
    float* WA = smem;
    float* WB = smem + SM_WB;
    float* Hs = smem + SM_HS;

    const float* gx_base = g_gx2[buf];
    const int tid = threadIdx.x;
    const int bid = blockIdx.x;
    const int nbA = bid * 16;   // rz column base (0..2047)
    const int nbB = bid * 8;    // n  column base (0..1023)

    // load weight slices once (k-major)
    for (int i = tid; i < 16 * 1024; i += 256) {
        int n = i >> 10, k = i & 1023;
        WA[k * 16 + n] = Whh[(size_t)(nbA + n) * HDIM + k];
    }
    for (int i = tid; i < 8 * 1024; i += 256) {
        int n = i >> 10, k = i & 1023;
        WB[k * 8 + n] = Whh[(size_t)(2048 + nbB + n) * HDIM + k];
    }

    const int b0  = (tid >> 3) * 2;   // 0..62
    const int n0A = (tid & 7) * 2;    // 0..14
    const int n0B = tid & 7;          // 0..7

    // per-thread load coordinates for 64x32 chunk staging
    const int bl  = tid >> 3;         // 0..31 (row for j=0; +32 for j=1)
    const int kk4 = (tid & 7) * 4;    // 0..28

    const float bA0 = bhh[nbA + n0A];
    const float bA1 = bhh[nbA + n0A + 1];
    const float bB  = bhh[2048 + nbB + n0B];
    const bool  is_r = (nbA < HDIM);

    __syncthreads();

    for (int tc = 0; tc < CHUNK; tc++) {
        const float* gx_t = gx_base + (size_t)tc * BATCH * G3;

        // ======== phase A: r/z gates (pipelined over k-chunks) ========
        float a00 = 0.f, a01 = 0.f, a10 = 0.f, a11 = 0.f;
        {
            // prologue: stage chunk 0
            float4 p0 = *(const float4*)&g_h[bl * HDIM + kk4];
            float4 p1 = *(const float4*)&g_h[(bl + 32) * HDIM + kk4];
            float* s0 = Hs;
            s0[(kk4 + 0) * 66 + bl] = p0.x; s0[(kk4 + 1) * 66 + bl] = p0.y;
            s0[(kk4 + 2) * 66 + bl] = p0.z; s0[(kk4 + 3) * 66 + bl] = p0.w;
            s0[(kk4 + 0) * 66 + bl + 32] = p1.x; s0[(kk4 + 1) * 66 + bl + 32] = p1.y;
            s0[(kk4 + 2) * 66 + bl + 32] = p1.z; s0[(kk4 + 3) * 66 + bl + 32] = p1.w;
            __syncthreads();

            for (int kc = 0; kc < 32; kc++) {
                float4 n0v, n1v;
                if (kc < 31) {
                    int k0 = (kc + 1) * 32;
                    n0v = *(const float4*)&g_h[bl * HDIM + k0 + kk4];
                    n1v = *(const float4*)&g_h[(bl + 32) * HDIM + k0 + kk4];
                }
                const float* cur = Hs + (kc & 1) * 2112;
                const float* wac = WA + kc * 32 * 16;
#pragma unroll
                for (int kk = 0; kk < 32; kk++) {
                    float2 h2 = *(const float2*)&cur[kk * 66 + b0];
                    float2 w2 = *(const float2*)&wac[kk * 16 + n0A];
                    a00 += h2.x * w2.x; a01 += h2.x * w2.y;
                    a10 += h2.y * w2.x; a11 += h2.y * w2.y;
                }
                if (kc < 31) {
                    float* nx = Hs + ((kc + 1) & 1) * 2112;
                    nx[(kk4 + 0) * 66 + bl] = n0v.x; nx[(kk4 + 1) * 66 + bl] = n0v.y;
                    nx[(kk4 + 2) * 66 + bl] = n0v.z; nx[(kk4 + 3) * 66 + bl] = n0v.w;
                    nx[(kk4 + 0) * 66 + bl + 32] = n1v.x; nx[(kk4 + 1) * 66 + bl + 32] = n1v.y;
                    nx[(kk4 + 2) * 66 + bl + 32] = n1v.z; nx[(kk4 + 3) * 66 + bl + 32] = n1v.w;
                }
                __syncthreads();
            }
        }
        {
            int n = nbA + n0A;
            float v00 = gx_t[(b0 + 0) * G3 + n]     + bA0 + a00;
            float v01 = gx_t[(b0 + 0) * G3 + n + 1] + bA1 + a01;
            float v10 = gx_t[(b0 + 1) * G3 + n]     + bA0 + a10;
            float v11 = gx_t[(b0 + 1) * G3 + n + 1] + bA1 + a11;
            float s00 = 1.f / (1.f + __expf(-v00));
            float s01 = 1.f / (1.f + __expf(-v01));
            float s10 = 1.f / (1.f + __expf(-v10));
            float s11 = 1.f / (1.f + __expf(-v11));
            if (is_r) {
                g_rh[(b0 + 0) * HDIM + n]     = s00 * g_h[(b0 + 0) * HDIM + n];
                g_rh[(b0 + 0) * HDIM + n + 1] = s01 * g_h[(b0 + 0) * HDIM + n + 1];
                g_rh[(b0 + 1) * HDIM + n]     = s10 * g_h[(b0 + 1) * HDIM + n];
                g_rh[(b0 + 1) * HDIM + n + 1] = s11 * g_h[(b0 + 1) * HDIM + n + 1];
            } else {
                int nz = n - HDIM;
                g_z[(b0 + 0) * HDIM + nz]     = s00;
                g_z[(b0 + 0) * HDIM + nz + 1] = s01;
                g_z[(b0 + 1) * HDIM + nz]     = s10;
                g_z[(b0 + 1) * HDIM + nz + 1] = s11;
            }
        }
        grid_sync();

        // ======== phase B: n gate + update (pipelined) ========
        float c0a = 0.f, c1a = 0.f;
        {
            float4 p0 = *(const float4*)&g_rh[bl * HDIM + kk4];
            float4 p1 = *(const float4*)&g_rh[(bl + 32) * HDIM + kk4];
            float* s0 = Hs;
            s0[(kk4 + 0) * 66 + bl] = p0.x; s0[(kk4 + 1) * 66 + bl] = p0.y;
            s0[(kk4 + 2) * 66 + bl] = p0.z; s0[(kk4 + 3) * 66 + bl] = p0.w;
            s0[(kk4 + 0) * 66 + bl + 32] = p1.x; s0[(kk4 + 1) * 66 + bl + 32] = p1.y;
            s0[(kk4 + 2) * 66 + bl + 32] = p1.z; s0[(kk4 + 3) * 66 + bl + 32] = p1.w;
            __syncthreads();

            for (int kc = 0; kc < 32; kc++) {
                float4 n0v, n1v;
                if (kc < 31) {
                    int k0 = (kc + 1) * 32;
                    n0v = *(const float4*)&g_rh[bl * HDIM + k0 + kk4];
                    n1v = *(const float4*)&g_rh[(bl + 32) * HDIM + k0 + kk4];
                }
                const float* cur = Hs + (kc & 1) * 2112;
                const float* wbc = WB + kc * 32 * 8;
#pragma unroll
                for (int kk = 0; kk < 32; kk++) {
                    float2 h2 = *(const float2*)&cur[kk * 66 + b0];
                    float  w  = wbc[kk * 8 + n0B];
                    c0a += h2.x * w;
                    c1a += h2.y * w;
                }
                if (kc < 31) {
                    float* nx = Hs + ((kc + 1) & 1) * 2112;
                    nx[(kk4 + 0) * 66 + bl] = n0v.x; nx[(kk4 + 1) * 66 + bl] = n0v.y;
                    nx[(kk4 + 2) * 66 + bl] = n0v.z; nx[(kk4 + 3) * 66 + bl] = n0v.w;
                    nx[(kk4 + 0) * 66 + bl + 32] = n1v.x; nx[(kk4 + 1) * 66 + bl + 32] = n1v.y;
                    nx[(kk4 + 2) * 66 + bl + 32] = n1v.z; nx[(kk4 + 3) * 66 + bl + 32] = n1v.w;
                }
                __syncthreads();
            }
        }
        {
            int n = nbB + n0B;
            int t = c0 + tc;
#pragma unroll
            for (int i = 0; i < 2; i++) {
                int b = b0 + i;
                float acc = (i == 0) ? c0a : c1a;
                float x = gx_t[b * G3 + 2048 + n] + bB + acc;
                float nv = 2.f / (1.f + __expf(-2.f * x)) - 1.f;   // tanh
                float z  = g_z[b * HDIM + n];
                float ho = g_h[b * HDIM + n];
                float hn = (1.f - z) * nv + z * ho;
                g_h[b * HDIM + n] = hn;
                Y[((size_t)t * BATCH + b) * HDIM + n] = hn;
            }
        }
        grid_sync();
    }
}

// ---------------- write Y_h ----------------
__global__ void write_yh_kernel(float* __restrict__ out_tail)
{
    int i = blockIdx.x * blockDim.x + threadIdx.x;
    if (i < BATCH * HDIM) out_tail[i] = g_h[i];
}

// ---------------- launch (gemm overlapped on a second stream) ----------------
extern "C" void kernel_launch(void* const* d_in, const int* in_sizes, int n_in,
                              void* d_out, int out_size)
{
    const float* input  = (const float*)d_in[0];
    const float* h0     = (const float*)d_in[1];
    const float* w_ih   = (const float*)d_in[2];
    const float* w_hh   = (const float*)d_in[3];
    const float* b_ih   = (const float*)d_in[4];
    const float* b_hh   = (const float*)d_in[5];
    float* out = (float*)d_out;

    static cudaStream_t s1 = nullptr;
    static cudaEvent_t evFork = nullptr;
    static cudaEvent_t evG[NCHUNK], evR[NCHUNK];
    if (s1 == nullptr) {
        cudaStreamCreateWithFlags(&s1, cudaStreamNonBlocking);
        cudaEventCreateWithFlags(&evFork, cudaEventDisableTiming);
        for (int c = 0; c < NCHUNK; c++) {
            cudaEventCreateWithFlags(&evG[c], cudaEventDisableTiming);
            cudaEventCreateWithFlags(&evR[c], cudaEventDisableTiming);
        }
        const int smem_bytes = SMEM_FLOATS * sizeof(float);
        cudaFuncSetAttribute(recurrence_kernel,
                             cudaFuncAttributeMaxDynamicSharedMemorySize, smem_bytes);
    }
    const int smem_bytes = SMEM_FLOATS * sizeof(float);

    init_h_kernel<<<(BATCH * HDIM + 255) / 256, 256>>>(h0);

    // fork: s1 joins the capture DAG
    cudaEventRecord(evFork, 0);
    cudaStreamWaitEvent(s1, evFork, 0);

    dim3 ggrid(G3 / 64, (CHUNK * BATCH) / 128);

    // prime two gemm chunks on s1
    gemm_gx_kernel<<<ggrid, 256, 0, s1>>>(input, w_ih, b_ih, 0);
    cudaEventRecord(evG[0], s1);
    gemm_gx_kernel<<<ggrid, 256, 0, s1>>>(input + (size_t)CHUNK * BATCH * IDIM, w_ih, b_ih, 1);
    cudaEventRecord(evG[1], s1);

    for (int c = 0; c < NCHUNK; c++) {
        cudaStreamWaitEvent(0, evG[c], 0);
        recurrence_kernel<<<NCTA, 256, smem_bytes>>>(c * CHUNK, c & 1, w_hh, b_hh, out);
        cudaEventRecord(evR[c], 0);
        if (c + 2 < NCHUNK) {
            cudaStreamWaitEvent(s1, evR[c], 0);   // buffer (c&1) free again
            gemm_gx_kernel<<<ggrid, 256, 0, s1>>>(
                input + (size_t)(c + 2) * CHUNK * BATCH * IDIM, w_ih, b_ih, (c + 2) & 1);
            cudaEventRecord(evG[c + 2], s1);
        }
    }

    write_yh_kernel<<<(BATCH * HDIM + 255) / 256, 256>>>(out + (size_t)SEQ * BATCH * HDIM);
}

// round 9
// speedup vs baseline: 1.2676x; 1.2676x over previous
// v3 resubmission — R7/R8 never reached the harness (broker failures)
#include <cuda_runtime.h>
#include <cstdint>

#define SEQ 512
#define BATCH 64
#define IDIM 1024
#define HDIM 1024
#define G3 3072
#define CHUNK 64
#define NCHUNK (SEQ / CHUNK)
#define NCTA 128

typedef unsigned long long ull;

// ---------------- scratch ----------------
__device__ float g_gx[(size_t)CHUNK * BATCH * G3];   // 50 MB
__device__ float g_h[BATCH * HDIM];
__device__ float g_z[BATCH * HDIM];
__device__ float g_rh[BATCH * HDIM];
__device__ float g_partA[4 * 32 * 64 * 64];          // [ks][ng][b][nc]
__device__ float g_partB[8 * 16 * 64 * 64];          // [ks][ng][b][nc]
__device__ unsigned g_flags[NCTA];                   // monotonic barrier flags

// ---------------- f32x2 helpers ----------------
__device__ __forceinline__ ull pack2(float x, float y) {
    ull r; asm("mov.b64 %0, {%1, %2};" : "=l"(r) : "f"(x), "f"(y)); return r;
}
__device__ __forceinline__ void unpack2(ull v, float& x, float& y) {
    asm("mov.b64 {%0, %1}, %2;" : "=f"(x), "=f"(y) : "l"(v));
}
__device__ __forceinline__ void fma2(ull& d, ull a, ull b) {
    asm("fma.rn.f32x2 %0, %1, %2, %0;" : "+l"(d) : "l"(a), "l"(b));
}

// ---------------- spin-safe flag access ----------------
__device__ __forceinline__ uint4 ld_flags4(const unsigned* p) {
    uint4 v;
    asm volatile("ld.global.cg.v4.u32 {%0,%1,%2,%3}, [%4];"
                 : "=r"(v.x), "=r"(v.y), "=r"(v.z), "=r"(v.w)
                 : "l"(p) : "memory");
    return v;
}
__device__ __forceinline__ void st_flag(unsigned* p, unsigned v) {
    asm volatile("st.global.cg.u32 [%0], %1;" :: "l"(p), "r"(v) : "memory");
}

// ---------------- flag-array grid barrier ----------------
__device__ __forceinline__ void bar_sync(int bid, unsigned target)
{
    __threadfence();            // every thread orders its own prior stores
    __syncthreads();
    if (threadIdx.x == 0) {
        st_flag(&g_flags[bid], target);
    }
    if (threadIdx.x < 32) {
        bool ok;
        int spins = 0;
        do {
            uint4 v = ld_flags4(&g_flags[threadIdx.x * 4]);
            ok = v.x >= target && v.y >= target && v.z >= target && v.w >= target;
            if (!ok && ++spins > 64) __nanosleep(128);
        } while (!__all_sync(0xffffffffu, ok));
        __threadfence();
    }
    __syncthreads();
}

// ---------------- gx GEMM (f32x2): C[4096,3072] = A @ W_ih^T + b ----------------
__global__ void __launch_bounds__(256) gemm_gx_kernel(
    const float* __restrict__ A, const float* __restrict__ W,
    const float* __restrict__ bias)
{
    __shared__ float As[16][132];
    __shared__ float Bs[16][68];

    const int bm = blockIdx.y * 128;
    const int bn = blockIdx.x * 64;
    const int tid = threadIdx.x;

    ull acc[8][2];
#pragma unroll
    for (int i = 0; i < 8; i++) { acc[i][0] = 0ull; acc[i][1] = 0ull; }

    const int tx = tid & 15;
    const int ty = tid >> 4;

    for (int k0 = 0; k0 < IDIM; k0 += 16) {
#pragma unroll
        for (int j = 0; j < 2; j++) {
            int lid = tid + j * 256;
            int row = lid >> 2;
            int kk  = (lid & 3) * 4;
            float4 v = *(const float4*)&A[(size_t)(bm + row) * IDIM + k0 + kk];
            As[kk + 0][row] = v.x; As[kk + 1][row] = v.y;
            As[kk + 2][row] = v.z; As[kk + 3][row] = v.w;
        }
        {
            int row = tid >> 2;
            int kk  = (tid & 3) * 4;
            float4 v = *(const float4*)&W[(size_t)(bn + row) * IDIM + k0 + kk];
            Bs[kk + 0][row] = v.x; Bs[kk + 1][row] = v.y;
            Bs[kk + 2][row] = v.z; Bs[kk + 3][row] = v.w;
        }
        __syncthreads();

#pragma unroll
        for (int kk = 0; kk < 16; kk++) {
            float4 a0 = *(const float4*)&As[kk][ty * 8];
            float4 a1 = *(const float4*)&As[kk][ty * 8 + 4];
            ulonglong2 b2 = *(const ulonglong2*)&Bs[kk][tx * 4];
            float av[8] = {a0.x, a0.y, a0.z, a0.w, a1.x, a1.y, a1.z, a1.w};
#pragma unroll
            for (int i = 0; i < 8; i++) {
                ull ad = pack2(av[i], av[i]);
                fma2(acc[i][0], ad, b2.x);
                fma2(acc[i][1], ad, b2.y);
            }
        }
        __syncthreads();
    }

#pragma unroll
    for (int i = 0; i < 8; i++) {
        int m = bm + ty * 8 + i;
        float c0, c1, c2, c3;
        unpack2(acc[i][0], c0, c1);
        unpack2(acc[i][1], c2, c3);
        int n = bn + tx * 4;
        g_gx[(size_t)m * G3 + n + 0] = c0 + bias[n + 0];
        g_gx[(size_t)m * G3 + n + 1] = c1 + bias[n + 1];
        g_gx[(size_t)m * G3 + n + 2] = c2 + bias[n + 2];
        g_gx[(size_t)m * G3 + n + 3] = c3 + bias[n + 3];
    }
}

// ---------------- init h ----------------
__global__ void init_h_kernel(const float* __restrict__ h0)
{
    int i = blockIdx.x * blockDim.x + threadIdx.x;
    if (i < BATCH * HDIM) g_h[i] = h0[i];
}

// ---------------- persistent recurrence ----------------
// smem: WsA[256][68], WsB[128][68], Hs[64][260]
#define SM_WA 0
#define SM_WB 17408
#define SM_HS 26112
#define SMEM_FLOATS (26112 + 64 * 260)

__global__ void __launch_bounds__(256, 1) recurrence_kernel(
    int c0, const float* __restrict__ Whh, const float* __restrict__ bhh,
    float* __restrict__ Y)
{
    extern __shared__ float sm[];
    float* WsA = sm + SM_WA;
    float* WsB = sm + SM_WB;
    float* Hs  = sm + SM_HS;

    const int tid = threadIdx.x;
    const int bid = blockIdx.x;
    const int gtid = bid * 256 + tid;

    // phase A role: 32 n-groups x 4 k-splits
    const int ngA = bid >> 2, ksA = bid & 3;
    const int nA0 = ngA * 64, kA0 = ksA * 256;
    // phase B role: 16 n-groups x 8 k-splits
    const int ngB = bid >> 3, ksB = bid & 7;
    const int nB0 = ngB * 64, kB0 = ksB * 128;

    // resident weights (once per launch)
    for (int idx = tid; idx < 64 * 256; idx += 256) {
        int n = idx >> 8, k = idx & 255;
        WsA[k * 68 + n] = __ldg(&Whh[(size_t)(nA0 + n) * HDIM + kA0 + k]);
    }
    for (int idx = tid; idx < 64 * 128; idx += 256) {
        int n = idx >> 7, k = idx & 127;
        WsB[k * 68 + n] = __ldg(&Whh[(size_t)(2048 + nB0 + n) * HDIM + kB0 + k]);
    }

    const int tx = tid & 15, ty = tid >> 4;
    const int b0 = ty * 4;
    const int cA = tx * 4;

    unsigned target;
    {
        unsigned t0;
        asm volatile("ld.global.cg.u32 %0, [%1];" : "=r"(t0)
                     : "l"(&g_flags[bid]) : "memory");
        target = t0;
    }

    __syncthreads();

    for (int tc = 0; tc < CHUNK; tc++) {
        const float* gx_t = g_gx + (size_t)tc * BATCH * G3;

        // ---- stage h slice [64 x 256] from kA0 ----
        for (int i4 = tid; i4 < 64 * 64; i4 += 256) {
            int b = i4 >> 6, c4 = (i4 & 63) * 4;
            float4 v = __ldcg((const float4*)&g_h[b * HDIM + kA0 + c4]);
            *(float4*)&Hs[b * 260 + c4] = v;
        }
        __syncthreads();

        // ---- phase A compute: partial[64b x 64n] over k in [kA0,kA0+256) ----
        {
            ull acc[4][2];
#pragma unroll
            for (int i = 0; i < 4; i++) { acc[i][0] = 0ull; acc[i][1] = 0ull; }

#pragma unroll 8
            for (int kk = 0; kk < 256; kk++) {
                ulonglong2 w2 = *(const ulonglong2*)&WsA[kk * 68 + cA];
                float h0v = Hs[(b0 + 0) * 260 + kk];
                float h1v = Hs[(b0 + 1) * 260 + kk];
                float h2v = Hs[(b0 + 2) * 260 + kk];
                float h3v = Hs[(b0 + 3) * 260 + kk];
                ull d0 = pack2(h0v, h0v), d1 = pack2(h1v, h1v);
                ull d2 = pack2(h2v, h2v), d3 = pack2(h3v, h3v);
                fma2(acc[0][0], d0, w2.x); fma2(acc[0][1], d0, w2.y);
                fma2(acc[1][0], d1, w2.x); fma2(acc[1][1], d1, w2.y);
                fma2(acc[2][0], d2, w2.x); fma2(acc[2][1], d2, w2.y);
                fma2(acc[3][0], d3, w2.x); fma2(acc[3][1], d3, w2.y);
            }

            float* pA = g_partA + ((size_t)(ksA * 32 + ngA)) * 4096;
#pragma unroll
            for (int i = 0; i < 4; i++) {
                float c0f, c1f, c2f, c3f;
                unpack2(acc[i][0], c0f, c1f);
                unpack2(acc[i][1], c2f, c3f);
                float4 v = make_float4(c0f, c1f, c2f, c3f);
                *(float4*)&pA[(b0 + i) * 64 + cA] = v;
            }
        }
        bar_sync(bid, ++target);

        // ---- phase A finalize: 4 gate elems / thread ----
        {
            int e0 = gtid * 4;
            int b = e0 >> 11, n = e0 & 2047;
            int png = n >> 6, pnc = n & 63;
            const float* base = g_partA + (size_t)png * 4096 + b * 64 + pnc;
            float4 s  = __ldcg((const float4*)(base + (size_t)0 * 32 * 4096));
            float4 p1 = __ldcg((const float4*)(base + (size_t)1 * 32 * 4096));
            float4 p2 = __ldcg((const float4*)(base + (size_t)2 * 32 * 4096));
            float4 p3 = __ldcg((const float4*)(base + (size_t)3 * 32 * 4096));
            s.x += p1.x + p2.x + p3.x; s.y += p1.y + p2.y + p3.y;
            s.z += p1.z + p2.z + p3.z; s.w += p1.w + p2.w + p3.w;
            float4 g = __ldg((const float4*)&gx_t[(size_t)b * G3 + n]);
            float4 bb = __ldg((const float4*)&bhh[n]);
            float s0 = 1.f / (1.f + __expf(-(s.x + g.x + bb.x)));
            float s1 = 1.f / (1.f + __expf(-(s.y + g.y + bb.y)));
            float s2 = 1.f / (1.f + __expf(-(s.z + g.z + bb.z)));
            float s3 = 1.f / (1.f + __expf(-(s.w + g.w + bb.w)));
            if (n < HDIM) {
                float4 h = __ldcg((const float4*)&g_h[b * HDIM + n]);
                float4 rh = make_float4(s0 * h.x, s1 * h.y, s2 * h.z, s3 * h.w);
                *(float4*)&g_rh[b * HDIM + n] = rh;
            } else {
                float4 zz = make_float4(s0, s1, s2, s3);
                *(float4*)&g_z[b * HDIM + (n - HDIM)] = zz;
            }
        }
        bar_sync(bid, ++target);

        // ---- stage rh slice [64 x 128] from kB0 ----
        for (int i4 = tid; i4 < 64 * 32; i4 += 256) {
            int b = i4 >> 5, c4 = (i4 & 31) * 4;
            float4 v = __ldcg((const float4*)&g_rh[b * HDIM + kB0 + c4]);
            *(float4*)&Hs[b * 132 + c4] = v;
        }
        __syncthreads();

        // ---- phase B compute: partial[64b x 64n] over k in [kB0,kB0+128) ----
        {
            ull acc[4][2];
#pragma unroll
            for (int i = 0; i < 4; i++) { acc[i][0] = 0ull; acc[i][1] = 0ull; }

#pragma unroll 8
            for (int kk = 0; kk < 128; kk++) {
                ulonglong2 w2 = *(const ulonglong2*)&WsB[kk * 68 + cA];
                float h0v = Hs[(b0 + 0) * 132 + kk];
                float h1v = Hs[(b0 + 1) * 132 + kk];
                float h2v = Hs[(b0 + 2) * 132 + kk];
                float h3v = Hs[(b0 + 3) * 132 + kk];
                ull d0 = pack2(h0v, h0v), d1 = pack2(h1v, h1v);
                ull d2 = pack2(h2v, h2v), d3 = pack2(h3v, h3v);
                fma2(acc[0][0], d0, w2.x); fma2(acc[0][1], d0, w2.y);
                fma2(acc[1][0], d1, w2.x); fma2(acc[1][1], d1, w2.y);
                fma2(acc[2][0], d2, w2.x); fma2(acc[2][1], d2, w2.y);
                fma2(acc[3][0], d3, w2.x); fma2(acc[3][1], d3, w2.y);
            }

            float* pB = g_partB + ((size_t)(ksB * 16 + ngB)) * 4096;
#pragma unroll
            for (int i = 0; i < 4; i++) {
                float c0f, c1f, c2f, c3f;
                unpack2(acc[i][0], c0f, c1f);
                unpack2(acc[i][1], c2f, c3f);
                float4 v = make_float4(c0f, c1f, c2f, c3f);
                *(float4*)&pB[(b0 + i) * 64 + cA] = v;
            }
        }
        bar_sync(bid, ++target);

        // ---- phase B finalize: 2 elems / thread ----
        {
            int e0 = gtid * 2;
            int b = e0 >> 10, n = e0 & 1023;
            int png = n >> 6, pnc = n & 63;
            const float* base = g_partB + (size_t)png * 4096 + b * 64 + pnc;
            float sx = 0.f, sy = 0.f;
#pragma unroll
            for (int ks = 0; ks < 8; ks++) {
                float2 p = __ldcg((const float2*)(base + (size_t)ks * 16 * 4096));
                sx += p.x; sy += p.y;
            }
            float2 g = __ldg((const float2*)&gx_t[(size_t)b * G3 + 2048 + n]);
            float2 bb = __ldg((const float2*)&bhh[2048 + n]);
            float x0 = sx + g.x + bb.x;
            float x1 = sy + g.y + bb.y;
            float n0 = 2.f / (1.f + __expf(-2.f * x0)) - 1.f;
            float n1 = 2.f / (1.f + __expf(-2.f * x1)) - 1.f;
            float2 z2 = __ldcg((const float2*)&g_z[b * HDIM + n]);
            float2 ho = __ldcg((const float2*)&g_h[b * HDIM + n]);
            float hn0 = (1.f - z2.x) * n0 + z2.x * ho.x;
            float hn1 = (1.f - z2.y) * n1 + z2.y * ho.y;
            *(float2*)&g_h[b * HDIM + n] = make_float2(hn0, hn1);
            int t = c0 + tc;
            *(float2*)&Y[((size_t)t * BATCH + b) * HDIM + n] = make_float2(hn0, hn1);
        }
        if (tc < CHUNK - 1) bar_sync(bid, ++target);
    }
}

// ---------------- write Y_h ----------------
__global__ void write_yh_kernel(float* __restrict__ out_tail)
{
    int i = blockIdx.x * blockDim.x + threadIdx.x;
    if (i < BATCH * HDIM) out_tail[i] = g_h[i];
}

// ---------------- launch (fully serialized, ~18 graph nodes) ----------------
extern "C" void kernel_launch(void* const* d_in, const int* in_sizes, int n_in,
                              void* d_out, int out_size)
{
    const float* input  = (const float*)d_in[0];
    const float* h0     = (const float*)d_in[1];
    const float* w_ih   = (const float*)d_in[2];
    const float* w_hh   = (const float*)d_in[3];
    const float* b_ih   = (const float*)d_in[4];
    const float* b_hh   = (const float*)d_in[5];
    float* out = (float*)d_out;

    const int smem_bytes = SMEM_FLOATS * sizeof(float);   // ~171 KB
    cudaFuncSetAttribute(recurrence_kernel,
                         cudaFuncAttributeMaxDynamicSharedMemorySize, smem_bytes);

    init_h_kernel<<<(BATCH * HDIM + 255) / 256, 256>>>(h0);

    dim3 ggrid(G3 / 64, (CHUNK * BATCH) / 128);
    for (int c = 0; c < NCHUNK; c++) {
        gemm_gx_kernel<<<ggrid, 256>>>(input + (size_t)c * CHUNK * BATCH * IDIM, w_ih, b_ih);
        recurrence_kernel<<<NCTA, 256, smem_bytes>>>(c * CHUNK, w_hh, b_hh, out);
    }

    write_yh_kernel<<<(BATCH * HDIM + 255) / 256, 256>>>(out + (size_t)SEQ * BATCH * HDIM);
}